// round 1
// baseline (speedup 1.0000x reference)
#include <cuda_runtime.h>

// Problem constants
#define BB    8
#define FF    6
#define FM1   5          // frames used (1..5)
#define NBUF  5
#define NSLOT 7
#define HH    192
#define WW    192
#define CC    3
#define HW    (HH*WW)    // 36864

#define TPB   256
#define BPI   18                       // blocks per (b,f) image; must divide 9216/256=36
#define NIMG  (BB*FM1)                 // 40
#define GRID_MAIN (NIMG*BPI)           // 720
#define VEC_PER_BLOCK (HW/4/BPI)       // 512 float4s per block
#define STEPS (VEC_PER_BLOCK/TPB)      // 2

#define EPSF   1e-7f
#define OMEPSF (1.0f - 1e-7f)

__device__ float g_partials[GRID_MAIN];

__device__ __forceinline__ void ld4(const float* __restrict__ p, float* o) {
    float4 v = *reinterpret_cast<const float4*>(p);
    o[0] = v.x; o[1] = v.y; o[2] = v.z; o[3] = v.w;
}

__global__ __launch_bounds__(TPB)
void em_main(const float* __restrict__ seg,
             const float* __restrict__ masks,
             const float* __restrict__ rec,
             const float* __restrict__ tgt,
             const float* __restrict__ vis,
             const float* __restrict__ attn)
{
    __shared__ float sAttnH[NSLOT][NBUF];  // attn * (1/HW)
    __shared__ float sAttnK[NSLOT][NBUF];  // attn * (0.1/C)
    __shared__ float sA[NBUF];             // (1/HW) * sum_s attn[s][n]

    const int img   = blockIdx.x / BPI;
    const int chunk = blockIdx.x % BPI;
    const int b = img / FM1;
    const int f = img % FM1 + 1;           // actual frame index (skip frame 0)

    const float invHW = 1.0f / (float)HW;
    const float Kc    = 0.1f / (float)CC;

    if (threadIdx.x < NSLOT * NBUF) {
        int s = threadIdx.x / NBUF, n = threadIdx.x % NBUF;
        float a = attn[((b*FF + f)*NSLOT + s)*NBUF + n];
        sAttnH[s][n] = a * invHW;
        sAttnK[s][n] = a * Kc;
    }
    __syncthreads();
    if (threadIdx.x < NBUF) {
        float sum = 0.0f;
        #pragma unroll
        for (int s = 0; s < NSLOT; s++) sum += sAttnH[s][threadIdx.x];
        sA[threadIdx.x] = sum;
    }
    __syncthreads();

    const int pixbase = chunk * VEC_PER_BLOCK * 4;     // element offset within image
    const int segoff  = (b*FF + f) * NBUF * HW;
    const int moff    = (b*FF + f) * NSLOT * HW;
    const int recoff  = (b*FF + f) * NBUF * CC * HW;
    const int toff    = (b*FF + f) * CC * HW;

    float acc[4] = {0.0f, 0.0f, 0.0f, 0.0f};

    for (int step = 0; step < STEPS; step++) {
        const int pix = pixbase + (step * TPB + (int)threadIdx.x) * 4;

        // --- reconstruction target (held across n loop) ---
        float tg[CC][4];
        #pragma unroll
        for (int c = 0; c < CC; c++) ld4(tgt + toff + c*HW + pix, tg[c]);

        // --- D[n] = sum_c (rec - tgt)^2 ---
        float D[NBUF][4];
        #pragma unroll
        for (int n = 0; n < NBUF; n++) {
            float d[4] = {0.0f, 0.0f, 0.0f, 0.0f};
            #pragma unroll
            for (int c = 0; c < CC; c++) {
                float r[4];
                ld4(rec + recoff + (n*CC + c)*HW + pix, r);
                #pragma unroll
                for (int j = 0; j < 4; j++) {
                    float dd = r[j] - tg[c][j];
                    d[j] = fmaf(dd, dd, d[j]);
                }
            }
            #pragma unroll
            for (int j = 0; j < 4; j++) D[n][j] = d[j];
        }

        // --- L[n] = log p - log(1-p); fold base term sum_n A'_n*log(1-p) ---
        float L[NBUF][4];
        #pragma unroll
        for (int n = 0; n < NBUF; n++) {
            float p[4];
            ld4(seg + segoff + n*HW + pix, p);
            const float An = sA[n];
            #pragma unroll
            for (int j = 0; j < 4; j++) {
                float pc  = fminf(fmaxf(p[j], EPSF), OMEPSF);
                float l1m = __logf(1.0f - pc);      // == log1p(-p) in fp32 (Sterbenz)
                float lp  = __logf(pc);
                L[n][j]   = lp - l1m;
                acc[j]    = fmaf(-An, l1m, acc[j]); // -(1/HW)*A_n*log(1-p)
            }
        }

        // --- slot loop: t/vis are {0,1} -> predicated adds ---
        #pragma unroll
        for (int s = 0; s < NSLOT; s++) {
            float m[4], v[4];
            ld4(masks + moff + s*HW + pix, m);
            ld4(vis   + moff + s*HW + pix, v);
            float aH[NBUF], aK[NBUF];
            #pragma unroll
            for (int n = 0; n < NBUF; n++) { aH[n] = sAttnH[s][n]; aK[n] = sAttnK[s][n]; }
            #pragma unroll
            for (int j = 0; j < 4; j++) {
                float tL = 0.0f, tV = 0.0f;
                #pragma unroll
                for (int n = 0; n < NBUF; n++) {
                    tL = fmaf(aH[n], L[n][j], tL);
                    tV = fmaf(aK[n], D[n][j], tV);
                }
                if (m[j] > 0.5f) acc[j] -= tL;  // -(1/HW) * L_n * t_s * attn
                if (v[j] > 0.5f) acc[j] += tV;  // +(0.1/C) * D_n * vis_s * attn
            }
        }
    }

    // --- block reduction ---
    float tot = (acc[0] + acc[1]) + (acc[2] + acc[3]);
    #pragma unroll
    for (int o = 16; o > 0; o >>= 1)
        tot += __shfl_down_sync(0xffffffffu, tot, o);

    __shared__ float wsum[TPB / 32];
    if ((threadIdx.x & 31) == 0) wsum[threadIdx.x >> 5] = tot;
    __syncthreads();
    if (threadIdx.x == 0) {
        float s = 0.0f;
        #pragma unroll
        for (int i = 0; i < TPB / 32; i++) s += wsum[i];
        g_partials[blockIdx.x] = s;
    }
}

__global__ __launch_bounds__(1024)
void em_final(float* __restrict__ out)
{
    __shared__ float ws[32];
    const int tid = threadIdx.x;
    float v = (tid < GRID_MAIN) ? g_partials[tid] : 0.0f;
    #pragma unroll
    for (int o = 16; o > 0; o >>= 1)
        v += __shfl_down_sync(0xffffffffu, v, o);
    if ((tid & 31) == 0) ws[tid >> 5] = v;
    __syncthreads();
    if (tid == 0) {
        double s = 0.0;
        #pragma unroll
        for (int i = 0; i < 32; i++) s += (double)ws[i];
        // total / (B*(F-1)*NB*NS) * LOSS_WEIGHT = total * 20/1400
        out[0] = (float)(s * (20.0 / 1400.0));
    }
}

extern "C" void kernel_launch(void* const* d_in, const int* in_sizes, int n_in,
                              void* d_out, int out_size)
{
    const float* seg   = (const float*)d_in[0];  // segmentations [B,F,NB,H,W]
    const float* masks = (const float*)d_in[1];  // masks         [B,F,NS,H,W]
    const float* rec   = (const float*)d_in[2];  // reconstructions [B,F,NB,C,H,W]
    const float* tgt   = (const float*)d_in[3];  // rec_tgt       [B,F,C,H,W]
    const float* vis   = (const float*)d_in[4];  // masks_vis     [B,F,NS,H,W]
    const float* attn  = (const float*)d_in[5];  // attn_index    [B,F,NS,NB]
    (void)in_sizes; (void)n_in; (void)out_size;

    em_main<<<GRID_MAIN, TPB>>>(seg, masks, rec, tgt, vis, attn);
    em_final<<<1, 1024>>>((float*)d_out);
}

// round 6
// speedup vs baseline: 1.1285x; 1.1285x over previous
#include <cuda_runtime.h>

// Problem constants
#define BB    8
#define FF    6
#define FM1   5          // frames used (1..5)
#define NBUF  5
#define NSLOT 7
#define HH    192
#define WW    192
#define CC    3
#define HW    (HH*WW)    // 36864

#define TPB   128
#define CHUNKS_PER_IMG (HW/4/TPB)      // 9216/128 = 72
#define NIMG  (BB*FM1)                 // 40
#define GRID_MAIN (NIMG*CHUNKS_PER_IMG) // 2880

#define EPSF   1e-7f
#define OMEPSF (1.0f - 1e-7f)

__device__ float g_partials[GRID_MAIN];
__device__ unsigned int g_ticket = 0;

__device__ __forceinline__ void ld4(const float* __restrict__ p, float* o) {
    float4 v = *reinterpret_cast<const float4*>(p);
    o[0] = v.x; o[1] = v.y; o[2] = v.z; o[3] = v.w;
}

__global__ __launch_bounds__(TPB)
void em_main(const float* __restrict__ seg,
             const float* __restrict__ masks,
             const float* __restrict__ rec,
             const float* __restrict__ tgt,
             const float* __restrict__ vis,
             const float* __restrict__ attn,
             float* __restrict__ out)
{
    __shared__ float sAttnH[NSLOT][NBUF];  // attn * (1/HW)
    __shared__ float sAttnK[NSLOT][NBUF];  // attn * (0.1/C)
    __shared__ float sA[NBUF];             // (1/HW) * sum_s attn[s][n]

    const int cid   = blockIdx.x;
    const int img   = cid / CHUNKS_PER_IMG;
    const int chunk = cid % CHUNKS_PER_IMG;
    const int b = img / FM1;
    const int f = img % FM1 + 1;           // skip frame 0
    const int base = b*FF + f;

    const float invHW = 1.0f / (float)HW;
    const float Kc    = 0.1f / (float)CC;

    if (threadIdx.x < NSLOT * NBUF) {
        int s = threadIdx.x / NBUF, n = threadIdx.x % NBUF;
        float a = attn[(base*NSLOT + s)*NBUF + n];
        sAttnH[s][n] = a * invHW;
        sAttnK[s][n] = a * Kc;
    }
    __syncthreads();
    if (threadIdx.x < NBUF) {
        float sum = 0.0f;
        #pragma unroll
        for (int s = 0; s < NSLOT; s++) sum += sAttnH[s][threadIdx.x];
        sA[threadIdx.x] = sum;
    }
    __syncthreads();

    const int pix = chunk * (TPB*4) + (int)threadIdx.x * 4;

    float acc[4] = {0.0f, 0.0f, 0.0f, 0.0f};

    // ================= Pass 1: BCE  (masks + seg) =================
    // T_n = sum_s attnH[s][n] * (mask_s > 0.5)
    float T[NBUF][4];
    #pragma unroll
    for (int n = 0; n < NBUF; n++)
        #pragma unroll
        for (int j = 0; j < 4; j++) T[n][j] = 0.0f;

    #pragma unroll
    for (int s = 0; s < NSLOT; s++) {
        float m[4];
        ld4(masks + (base*NSLOT + s)*HW + pix, m);
        float aH[NBUF];
        #pragma unroll
        for (int n = 0; n < NBUF; n++) aH[n] = sAttnH[s][n];
        #pragma unroll
        for (int j = 0; j < 4; j++) {
            bool tb = m[j] > 0.5f;
            #pragma unroll
            for (int n = 0; n < NBUF; n++)
                T[n][j] += tb ? aH[n] : 0.0f;
        }
    }

    // acc -= T_n*logp + (A_n - T_n)*log(1-p)
    #pragma unroll
    for (int n = 0; n < NBUF; n++) {
        float p[4];
        ld4(seg + (base*NBUF + n)*HW + pix, p);
        const float An = sA[n];
        #pragma unroll
        for (int j = 0; j < 4; j++) {
            float pc  = fminf(fmaxf(p[j], EPSF), OMEPSF);
            float lp  = __logf(pc);
            float l1m = __logf(1.0f - pc);      // == log1p(-p) in fp32 (Sterbenz)
            float Tn  = T[n][j];
            acc[j] = fmaf(-Tn, lp, acc[j]);
            acc[j] = fmaf(Tn - An, l1m, acc[j]);
        }
    }

    // ================= Pass 2: masked MSE  (vis + tgt + rec) =================
    // V_n = sum_s attnK[s][n] * (vis_s > 0.5)   (reuses T's registers)
    float V[NBUF][4];
    #pragma unroll
    for (int n = 0; n < NBUF; n++)
        #pragma unroll
        for (int j = 0; j < 4; j++) V[n][j] = 0.0f;

    #pragma unroll
    for (int s = 0; s < NSLOT; s++) {
        float v[4];
        ld4(vis + (base*NSLOT + s)*HW + pix, v);
        float aK[NBUF];
        #pragma unroll
        for (int n = 0; n < NBUF; n++) aK[n] = sAttnK[s][n];
        #pragma unroll
        for (int j = 0; j < 4; j++) {
            bool vb = v[j] > 0.5f;
            #pragma unroll
            for (int n = 0; n < NBUF; n++)
                V[n][j] += vb ? aK[n] : 0.0f;
        }
    }

    float tg[CC][4];
    #pragma unroll
    for (int c = 0; c < CC; c++) ld4(tgt + (base*CC + c)*HW + pix, tg[c]);

    #pragma unroll
    for (int n = 0; n < NBUF; n++) {
        float d2[4] = {0.0f, 0.0f, 0.0f, 0.0f};
        #pragma unroll
        for (int c = 0; c < CC; c++) {
            float r[4];
            ld4(rec + ((base*NBUF + n)*CC + c)*HW + pix, r);
            #pragma unroll
            for (int j = 0; j < 4; j++) {
                float dd = r[j] - tg[c][j];
                d2[j] = fmaf(dd, dd, d2[j]);
            }
        }
        #pragma unroll
        for (int j = 0; j < 4; j++)
            acc[j] = fmaf(V[n][j], d2[j], acc[j]);
    }

    // ================= block reduction =================
    float tot = (acc[0] + acc[1]) + (acc[2] + acc[3]);
    #pragma unroll
    for (int o = 16; o > 0; o >>= 1)
        tot += __shfl_down_sync(0xffffffffu, tot, o);

    __shared__ float wsum[TPB / 32];
    if ((threadIdx.x & 31) == 0) wsum[threadIdx.x >> 5] = tot;
    __syncthreads();

    __shared__ bool isLast;
    if (threadIdx.x == 0) {
        float s = 0.0f;
        #pragma unroll
        for (int i = 0; i < TPB / 32; i++) s += wsum[i];
        g_partials[blockIdx.x] = s;
        __threadfence();
        unsigned prev = atomicAdd(&g_ticket, 1u);
        isLast = (prev == GRID_MAIN - 1);
    }
    __syncthreads();

    // ================= last block: final deterministic reduction =================
    if (isLast) {
        float v = 0.0f;
        for (int i = (int)threadIdx.x; i < GRID_MAIN; i += TPB)
            v += g_partials[i];                 // fixed strided order -> deterministic
        #pragma unroll
        for (int o = 16; o > 0; o >>= 1)
            v += __shfl_down_sync(0xffffffffu, v, o);
        if ((threadIdx.x & 31) == 0) wsum[threadIdx.x >> 5] = v;
        __syncthreads();
        if (threadIdx.x == 0) {
            float s = 0.0f;
            #pragma unroll
            for (int i = 0; i < TPB / 32; i++) s += wsum[i];
            // total / (B*(F-1)*NB*NS) * LOSS_WEIGHT = total * 20/1400
            out[0] = s * (20.0f / 1400.0f);
            atomicExch(&g_ticket, 0u);          // reset for next graph replay
        }
    }
}

extern "C" void kernel_launch(void* const* d_in, const int* in_sizes, int n_in,
                              void* d_out, int out_size)
{
    const float* seg   = (const float*)d_in[0];  // segmentations   [B,F,NB,H,W]
    const float* masks = (const float*)d_in[1];  // masks           [B,F,NS,H,W]
    const float* rec   = (const float*)d_in[2];  // reconstructions [B,F,NB,C,H,W]
    const float* tgt   = (const float*)d_in[3];  // rec_tgt         [B,F,C,H,W]
    const float* vis   = (const float*)d_in[4];  // masks_vis       [B,F,NS,H,W]
    const float* attn  = (const float*)d_in[5];  // attn_index      [B,F,NS,NB]
    (void)in_sizes; (void)n_in; (void)out_size;

    em_main<<<GRID_MAIN, TPB>>>(seg, masks, rec, tgt, vis, attn, (float*)d_out);
}

// round 7
// speedup vs baseline: 1.1301x; 1.0014x over previous
#include <cuda_runtime.h>

// Problem constants
#define BB    8
#define FF    6
#define FM1   5          // frames used (1..5)
#define NBUF  5
#define NSLOT 7
#define HH    192
#define WW    192
#define CC    3
#define HW    (HH*WW)    // 36864

#define TPB   64
#define CHUNK_PX (TPB*4)                    // 256 pixels per block
#define CHUNKS_PER_IMG (HW/CHUNK_PX)        // 144
#define NIMG  (BB*FM1)                      // 40
#define GRID_MAIN (NIMG*CHUNKS_PER_IMG)     // 5760

#define EPSF   1e-7f
#define OMEPSF (1.0f - 1e-7f)

__device__ float g_partials[GRID_MAIN];
__device__ unsigned int g_ticket = 0;

__device__ __forceinline__ void ld4s(const float* __restrict__ p, float* o) {
    float4 v = __ldcs(reinterpret_cast<const float4*>(p));   // streaming, evict-first
    o[0] = v.x; o[1] = v.y; o[2] = v.z; o[3] = v.w;
}

__global__ __launch_bounds__(TPB, 16)
void em_main(const float* __restrict__ seg,
             const float* __restrict__ masks,
             const float* __restrict__ rec,
             const float* __restrict__ tgt,
             const float* __restrict__ vis,
             const float* __restrict__ attn,
             float* __restrict__ out)
{
    __shared__ float sAttnH[NSLOT][NBUF];  // attn * (1/HW)
    __shared__ float sAttnK[NSLOT][NBUF];  // attn * (0.1/C)
    __shared__ float sA[NBUF];             // (1/HW) * sum_s attn[s][n]

    const int cid   = blockIdx.x;
    const int img   = cid / CHUNKS_PER_IMG;
    const int chunk = cid % CHUNKS_PER_IMG;
    const int b = img / FM1;
    const int f = img % FM1 + 1;           // skip frame 0
    const int base = b*FF + f;

    const float invHW = 1.0f / (float)HW;
    const float Kc    = 0.1f / (float)CC;

    if (threadIdx.x < NSLOT * NBUF) {
        int s = threadIdx.x / NBUF, n = threadIdx.x % NBUF;
        float a = attn[(base*NSLOT + s)*NBUF + n];
        sAttnH[s][n] = a * invHW;
        sAttnK[s][n] = a * Kc;
    }
    __syncthreads();
    if (threadIdx.x < NBUF) {
        float sum = 0.0f;
        #pragma unroll
        for (int s = 0; s < NSLOT; s++) sum += sAttnH[s][threadIdx.x];
        sA[threadIdx.x] = sum;
    }
    __syncthreads();

    const int pix = chunk * CHUNK_PX + (int)threadIdx.x * 4;

    float acc[4] = {0.0f, 0.0f, 0.0f, 0.0f};

    // ================= Pass 1: BCE  (masks + seg) =================
    // T_n = sum_s attnH[s][n] * (mask_s > 0.5)  -- bool->float, pure FFMA
    float T[NBUF][4];
    #pragma unroll
    for (int n = 0; n < NBUF; n++)
        #pragma unroll
        for (int j = 0; j < 4; j++) T[n][j] = 0.0f;

    #pragma unroll
    for (int s = 0; s < NSLOT; s++) {
        float m[4];
        ld4s(masks + (base*NSLOT + s)*HW + pix, m);
        float aH[NBUF];
        #pragma unroll
        for (int n = 0; n < NBUF; n++) aH[n] = sAttnH[s][n];
        #pragma unroll
        for (int j = 0; j < 4; j++) {
            float tb = (m[j] > 0.5f) ? 1.0f : 0.0f;
            #pragma unroll
            for (int n = 0; n < NBUF; n++)
                T[n][j] = fmaf(tb, aH[n], T[n][j]);
        }
    }

    // acc -= T_n*logp + (A_n - T_n)*log(1-p)
    #pragma unroll
    for (int n = 0; n < NBUF; n++) {
        float p[4];
        ld4s(seg + (base*NBUF + n)*HW + pix, p);
        const float An = sA[n];
        #pragma unroll
        for (int j = 0; j < 4; j++) {
            float pc  = fminf(fmaxf(p[j], EPSF), OMEPSF);
            float lp  = __logf(pc);
            float l1m = __logf(1.0f - pc);      // == log1p(-p) in fp32 (Sterbenz)
            float Tn  = T[n][j];
            acc[j] = fmaf(-Tn, lp, acc[j]);
            acc[j] = fmaf(Tn - An, l1m, acc[j]);
        }
    }

    // ================= Pass 2: masked MSE  (vis + tgt + rec) =================
    float V[NBUF][4];
    #pragma unroll
    for (int n = 0; n < NBUF; n++)
        #pragma unroll
        for (int j = 0; j < 4; j++) V[n][j] = 0.0f;

    #pragma unroll
    for (int s = 0; s < NSLOT; s++) {
        float v[4];
        ld4s(vis + (base*NSLOT + s)*HW + pix, v);
        float aK[NBUF];
        #pragma unroll
        for (int n = 0; n < NBUF; n++) aK[n] = sAttnK[s][n];
        #pragma unroll
        for (int j = 0; j < 4; j++) {
            float vb = (v[j] > 0.5f) ? 1.0f : 0.0f;
            #pragma unroll
            for (int n = 0; n < NBUF; n++)
                V[n][j] = fmaf(vb, aK[n], V[n][j]);
        }
    }

    float tg[CC][4];
    #pragma unroll
    for (int c = 0; c < CC; c++) ld4s(tgt + (base*CC + c)*HW + pix, tg[c]);

    #pragma unroll
    for (int n = 0; n < NBUF; n++) {
        float d2[4] = {0.0f, 0.0f, 0.0f, 0.0f};
        #pragma unroll
        for (int c = 0; c < CC; c++) {
            float r[4];
            ld4s(rec + ((base*NBUF + n)*CC + c)*HW + pix, r);
            #pragma unroll
            for (int j = 0; j < 4; j++) {
                float dd = r[j] - tg[c][j];
                d2[j] = fmaf(dd, dd, d2[j]);
            }
        }
        #pragma unroll
        for (int j = 0; j < 4; j++)
            acc[j] = fmaf(V[n][j], d2[j], acc[j]);
    }

    // ================= block reduction (2 warps) =================
    float tot = (acc[0] + acc[1]) + (acc[2] + acc[3]);
    #pragma unroll
    for (int o = 16; o > 0; o >>= 1)
        tot += __shfl_down_sync(0xffffffffu, tot, o);

    __shared__ float wsum[TPB / 32];
    if ((threadIdx.x & 31) == 0) wsum[threadIdx.x >> 5] = tot;
    __syncthreads();

    __shared__ bool isLast;
    if (threadIdx.x == 0) {
        float s = 0.0f;
        #pragma unroll
        for (int i = 0; i < TPB / 32; i++) s += wsum[i];
        g_partials[blockIdx.x] = s;
        __threadfence();
        unsigned prev = atomicAdd(&g_ticket, 1u);
        isLast = (prev == GRID_MAIN - 1);
    }
    __syncthreads();

    // ================= last block: final deterministic reduction =================
    if (isLast) {
        // 5760 / 64 = 90 elements per thread; 4 independent accumulators for ILP,
        // fixed combination order -> deterministic.
        float v0 = 0.0f, v1 = 0.0f, v2 = 0.0f, v3 = 0.0f;
        #pragma unroll 1
        for (int i = (int)threadIdx.x; i < GRID_MAIN; i += TPB * 4) {
            v0 += g_partials[i];
            v1 += g_partials[i + TPB];
            v2 += g_partials[i + 2*TPB];
            v3 += g_partials[i + 3*TPB];
        }
        float v = (v0 + v1) + (v2 + v3);
        #pragma unroll
        for (int o = 16; o > 0; o >>= 1)
            v += __shfl_down_sync(0xffffffffu, v, o);
        if ((threadIdx.x & 31) == 0) wsum[threadIdx.x >> 5] = v;
        __syncthreads();
        if (threadIdx.x == 0) {
            float s = 0.0f;
            #pragma unroll
            for (int i = 0; i < TPB / 32; i++) s += wsum[i];
            // total / (B*(F-1)*NB*NS) * LOSS_WEIGHT = total * 20/1400
            out[0] = s * (20.0f / 1400.0f);
            atomicExch(&g_ticket, 0u);          // reset for next graph replay
        }
    }
}

extern "C" void kernel_launch(void* const* d_in, const int* in_sizes, int n_in,
                              void* d_out, int out_size)
{
    const float* seg   = (const float*)d_in[0];  // segmentations   [B,F,NB,H,W]
    const float* masks = (const float*)d_in[1];  // masks           [B,F,NS,H,W]
    const float* rec   = (const float*)d_in[2];  // reconstructions [B,F,NB,C,H,W]
    const float* tgt   = (const float*)d_in[3];  // rec_tgt         [B,F,C,H,W]
    const float* vis   = (const float*)d_in[4];  // masks_vis       [B,F,NS,H,W]
    const float* attn  = (const float*)d_in[5];  // attn_index      [B,F,NS,NB]
    (void)in_sizes; (void)n_in; (void)out_size;

    em_main<<<GRID_MAIN, TPB>>>(seg, masks, rec, tgt, vis, attn, (float*)d_out);
}

// round 9
// speedup vs baseline: 1.1626x; 1.0288x over previous
#include <cuda_runtime.h>

// Problem constants
#define BB    8
#define FF    6
#define FM1   5          // frames used (1..5)
#define NBUF  5
#define NSLOT 7
#define HH    192
#define WW    192
#define CC    3
#define HW    (HH*WW)    // 36864

#define TPB   128
#define VW    2                             // float2 vectorization
#define CHUNK_PX (TPB*VW)                   // 256 pixels per block
#define CHUNKS_PER_IMG (HW/CHUNK_PX)        // 144
#define NIMG  (BB*FM1)                      // 40
#define GRID_MAIN (NIMG*CHUNKS_PER_IMG)     // 5760

#define EPSF   1e-7f
#define OMEPSF (1.0f - 1e-7f)

__device__ float g_partials[GRID_MAIN];
__device__ unsigned int g_ticket = 0;

__device__ __forceinline__ void ld2s(const float* __restrict__ p, float* o) {
    float2 v = __ldcs(reinterpret_cast<const float2*>(p));   // streaming, evict-first
    o[0] = v.x; o[1] = v.y;
}

__global__ __launch_bounds__(TPB)
void em_main(const float* __restrict__ seg,
             const float* __restrict__ masks,
             const float* __restrict__ rec,
             const float* __restrict__ tgt,
             const float* __restrict__ vis,
             const float* __restrict__ attn,
             float* __restrict__ out)
{
    __shared__ float sAttnH[NSLOT][NBUF];  // attn * (1/HW)
    __shared__ float sAttnK[NSLOT][NBUF];  // attn * (0.1/C)
    __shared__ float sA[NBUF];             // (1/HW) * sum_s attn[s][n]

    const int cid   = blockIdx.x;
    const int img   = cid / CHUNKS_PER_IMG;
    const int chunk = cid % CHUNKS_PER_IMG;
    const int b = img / FM1;
    const int f = img % FM1 + 1;           // skip frame 0
    const int base = b*FF + f;

    const float invHW = 1.0f / (float)HW;
    const float Kc    = 0.1f / (float)CC;

    if (threadIdx.x < NSLOT * NBUF) {
        int s = threadIdx.x / NBUF, n = threadIdx.x % NBUF;
        float a = attn[(base*NSLOT + s)*NBUF + n];
        sAttnH[s][n] = a * invHW;
        sAttnK[s][n] = a * Kc;
    }
    __syncthreads();
    if (threadIdx.x < NBUF) {
        float sum = 0.0f;
        #pragma unroll
        for (int s = 0; s < NSLOT; s++) sum += sAttnH[s][threadIdx.x];
        sA[threadIdx.x] = sum;
    }
    __syncthreads();

    const int pix = chunk * CHUNK_PX + (int)threadIdx.x * VW;

    float acc[VW] = {0.0f, 0.0f};

    // ================= Pass 1: BCE  (masks + seg) =================
    // T_n = sum_s attnH[s][n] * (mask_s > 0.5)
    float T[NBUF][VW];
    #pragma unroll
    for (int n = 0; n < NBUF; n++)
        #pragma unroll
        for (int j = 0; j < VW; j++) T[n][j] = 0.0f;

    #pragma unroll
    for (int s = 0; s < NSLOT; s++) {
        float m[VW];
        ld2s(masks + (base*NSLOT + s)*HW + pix, m);
        float aH[NBUF];
        #pragma unroll
        for (int n = 0; n < NBUF; n++) aH[n] = sAttnH[s][n];
        #pragma unroll
        for (int j = 0; j < VW; j++) {
            float tb = (m[j] > 0.5f) ? 1.0f : 0.0f;
            #pragma unroll
            for (int n = 0; n < NBUF; n++)
                T[n][j] = fmaf(tb, aH[n], T[n][j]);
        }
    }

    // acc -= T_n*logp + (A_n - T_n)*log(1-p)
    #pragma unroll
    for (int n = 0; n < NBUF; n++) {
        float p[VW];
        ld2s(seg + (base*NBUF + n)*HW + pix, p);
        const float An = sA[n];
        #pragma unroll
        for (int j = 0; j < VW; j++) {
            float pc  = fminf(fmaxf(p[j], EPSF), OMEPSF);
            float lp  = __logf(pc);
            float l1m = __logf(1.0f - pc);      // == log1p(-p) in fp32 (Sterbenz)
            float Tn  = T[n][j];
            acc[j] = fmaf(-Tn, lp, acc[j]);
            acc[j] = fmaf(Tn - An, l1m, acc[j]);
        }
    }

    // ================= Pass 2: masked MSE  (vis + tgt + rec) =================
    float V[NBUF][VW];
    #pragma unroll
    for (int n = 0; n < NBUF; n++)
        #pragma unroll
        for (int j = 0; j < VW; j++) V[n][j] = 0.0f;

    #pragma unroll
    for (int s = 0; s < NSLOT; s++) {
        float v[VW];
        ld2s(vis + (base*NSLOT + s)*HW + pix, v);
        float aK[NBUF];
        #pragma unroll
        for (int n = 0; n < NBUF; n++) aK[n] = sAttnK[s][n];
        #pragma unroll
        for (int j = 0; j < VW; j++) {
            float vb = (v[j] > 0.5f) ? 1.0f : 0.0f;
            #pragma unroll
            for (int n = 0; n < NBUF; n++)
                V[n][j] = fmaf(vb, aK[n], V[n][j]);
        }
    }

    float tg[CC][VW];
    #pragma unroll
    for (int c = 0; c < CC; c++) ld2s(tgt + (base*CC + c)*HW + pix, tg[c]);

    #pragma unroll
    for (int n = 0; n < NBUF; n++) {
        float d2[VW] = {0.0f, 0.0f};
        #pragma unroll
        for (int c = 0; c < CC; c++) {
            float r[VW];
            ld2s(rec + ((base*NBUF + n)*CC + c)*HW + pix, r);
            #pragma unroll
            for (int j = 0; j < VW; j++) {
                float dd = r[j] - tg[c][j];
                d2[j] = fmaf(dd, dd, d2[j]);
            }
        }
        #pragma unroll
        for (int j = 0; j < VW; j++)
            acc[j] = fmaf(V[n][j], d2[j], acc[j]);
    }

    // ================= block reduction =================
    float tot = acc[0] + acc[1];
    #pragma unroll
    for (int o = 16; o > 0; o >>= 1)
        tot += __shfl_down_sync(0xffffffffu, tot, o);

    __shared__ float wsum[TPB / 32];
    if ((threadIdx.x & 31) == 0) wsum[threadIdx.x >> 5] = tot;
    __syncthreads();

    __shared__ bool isLast;
    if (threadIdx.x == 0) {
        float s = 0.0f;
        #pragma unroll
        for (int i = 0; i < TPB / 32; i++) s += wsum[i];
        g_partials[blockIdx.x] = s;
        __threadfence();
        unsigned prev = atomicAdd(&g_ticket, 1u);
        isLast = (prev == GRID_MAIN - 1);
    }
    __syncthreads();

    // ================= last block: final deterministic reduction =================
    if (isLast) {
        // 5760 / 128 = 45 per thread; fixed strided order -> deterministic.
        float v0 = 0.0f, v1 = 0.0f, v2 = 0.0f;
        #pragma unroll 1
        for (int i = (int)threadIdx.x; i < GRID_MAIN; i += TPB * 3) {
            v0 += g_partials[i];
            v1 += g_partials[i + TPB];
            v2 += g_partials[i + 2*TPB];
        }
        float v = (v0 + v1) + v2;
        #pragma unroll
        for (int o = 16; o > 0; o >>= 1)
            v += __shfl_down_sync(0xffffffffu, v, o);
        if ((threadIdx.x & 31) == 0) wsum[threadIdx.x >> 5] = v;
        __syncthreads();
        if (threadIdx.x == 0) {
            float s = 0.0f;
            #pragma unroll
            for (int i = 0; i < TPB / 32; i++) s += wsum[i];
            // total / (B*(F-1)*NB*NS) * LOSS_WEIGHT = total * 20/1400
            out[0] = s * (20.0f / 1400.0f);
            atomicExch(&g_ticket, 0u);          // reset for next graph replay
        }
    }
}

extern "C" void kernel_launch(void* const* d_in, const int* in_sizes, int n_in,
                              void* d_out, int out_size)
{
    const float* seg   = (const float*)d_in[0];  // segmentations   [B,F,NB,H,W]
    const float* masks = (const float*)d_in[1];  // masks           [B,F,NS,H,W]
    const float* rec   = (const float*)d_in[2];  // reconstructions [B,F,NB,C,H,W]
    const float* tgt   = (const float*)d_in[3];  // rec_tgt         [B,F,C,H,W]
    const float* vis   = (const float*)d_in[4];  // masks_vis       [B,F,NS,H,W]
    const float* attn  = (const float*)d_in[5];  // attn_index      [B,F,NS,NB]
    (void)in_sizes; (void)n_in; (void)out_size;

    em_main<<<GRID_MAIN, TPB>>>(seg, masks, rec, tgt, vis, attn, (float*)d_out);
}

// round 11
// speedup vs baseline: 1.1882x; 1.0221x over previous
#include <cuda_runtime.h>
#include <cstdint>

// Problem constants
#define BB    8
#define FF    6
#define FM1   5          // frames used (1..5)
#define NBUF  5
#define NSLOT 7
#define HH    192
#define WW    192
#define CC    3
#define HW    (HH*WW)    // 36864

#define TPB   128
#define CHUNK_PX 256                        // pixels per block
#define CHUNKS_PER_IMG (HW/CHUNK_PX)        // 144
#define NIMG  (BB*FM1)                      // 40
#define GRID_MAIN (NIMG*CHUNKS_PER_IMG)     // 5760

// Stream layout in SMEM (each stream = CHUNK_PX floats = 1KB)
// 0..6   masks s            (group 0)
// 7..11  seg n              (group 0)
// 12..18 vis s              (group 1)
// 19..21 tgt c              (group 1)
// 22..36 rec n*3+c          (group 2)
#define NSTREAM 37

#define EPSF   1e-7f
#define OMEPSF (1.0f - 1e-7f)

__device__ float g_partials[GRID_MAIN];
__device__ unsigned int g_ticket = 0;

__device__ __forceinline__ void cpa16(uint32_t saddr, const float* __restrict__ g) {
    asm volatile("cp.async.cg.shared.global [%0], [%1], 16;\n" :: "r"(saddr), "l"(g));
}

__global__ __launch_bounds__(TPB)
void em_main(const float* __restrict__ seg,
             const float* __restrict__ masks,
             const float* __restrict__ rec,
             const float* __restrict__ tgt,
             const float* __restrict__ vis,
             const float* __restrict__ attn,
             float* __restrict__ out)
{
    __shared__ float sm_data[NSTREAM * CHUNK_PX];   // 37 KB
    __shared__ float sAttnH[NSLOT][NBUF];           // attn * (1/HW)
    __shared__ float sAttnK[NSLOT][NBUF];           // attn * (0.1/C)
    __shared__ float sA[NBUF];                      // (1/HW) * sum_s attn[s][n]
    __shared__ float wsum[TPB / 32];
    __shared__ bool  isLast;

    const int tid   = (int)threadIdx.x;
    const int cid   = (int)blockIdx.x;
    const int img   = cid / CHUNKS_PER_IMG;
    const int chunk = cid % CHUNKS_PER_IMG;
    const int b = img / FM1;
    const int f = img % FM1 + 1;           // skip frame 0
    const int base = b*FF + f;
    const int pix0 = chunk * CHUNK_PX;

    // ---------------- issue all async copies ----------------
    const uint32_t smem0 = (uint32_t)__cvta_generic_to_shared(sm_data);
    const int half = tid >> 6;             // 0/1: which stream of the pair
    const int unit = tid & 63;             // 16B unit within stream (64 units = 1KB)
    const int goff = unit * 4;             // float offset of this unit

    // group 0: masks (7) + seg (5)
    #pragma unroll
    for (int s = 0; s < NSLOT; s += 2) {
        int ss = s + half;
        if (ss < NSLOT)
            cpa16(smem0 + (uint32_t)(ss*CHUNK_PX + goff)*4u,
                  masks + (size_t)(base*NSLOT + ss)*HW + pix0 + goff);
    }
    #pragma unroll
    for (int n = 0; n < NBUF; n += 2) {
        int nn = n + half;
        if (nn < NBUF)
            cpa16(smem0 + (uint32_t)((7+nn)*CHUNK_PX + goff)*4u,
                  seg + (size_t)(base*NBUF + nn)*HW + pix0 + goff);
    }
    asm volatile("cp.async.commit_group;\n" ::: "memory");

    // group 1: vis (7) + tgt (3)
    #pragma unroll
    for (int s = 0; s < NSLOT; s += 2) {
        int ss = s + half;
        if (ss < NSLOT)
            cpa16(smem0 + (uint32_t)((12+ss)*CHUNK_PX + goff)*4u,
                  vis + (size_t)(base*NSLOT + ss)*HW + pix0 + goff);
    }
    #pragma unroll
    for (int c = 0; c < CC; c += 2) {
        int cc2 = c + half;
        if (cc2 < CC)
            cpa16(smem0 + (uint32_t)((19+cc2)*CHUNK_PX + goff)*4u,
                  tgt + (size_t)(base*CC + cc2)*HW + pix0 + goff);
    }
    asm volatile("cp.async.commit_group;\n" ::: "memory");

    // group 2: rec (15)
    #pragma unroll
    for (int k = 0; k < NBUF*CC; k += 2) {
        int kk = k + half;
        if (kk < NBUF*CC)
            cpa16(smem0 + (uint32_t)((22+kk)*CHUNK_PX + goff)*4u,
                  rec + (size_t)(base*NBUF*CC + kk)*HW + pix0 + goff);
    }
    asm volatile("cp.async.commit_group;\n" ::: "memory");

    // ---------------- attn coefficients (overlaps copies) ----------------
    const float invHW = 1.0f / (float)HW;
    const float Kc    = 0.1f / (float)CC;
    if (tid < NSLOT * NBUF) {
        int s = tid / NBUF, n = tid % NBUF;
        float a = attn[(base*NSLOT + s)*NBUF + n];
        sAttnH[s][n] = a * invHW;
        sAttnK[s][n] = a * Kc;
    }
    __syncthreads();
    if (tid < NBUF) {
        float sum = 0.0f;
        #pragma unroll
        for (int s = 0; s < NSLOT; s++) sum += sAttnH[s][tid];
        sA[tid] = sum;
    }

    const float2* sm2 = reinterpret_cast<const float2*>(sm_data);
    #define SM2(s) sm2[(s)*(CHUNK_PX/2) + tid]

    float acc[2] = {0.0f, 0.0f};

    // ================= Phase A: BCE (needs group 0) =================
    asm volatile("cp.async.wait_group 2;\n" ::: "memory");
    __syncthreads();   // group-0 data + sA visible to all

    float T[NBUF][2];
    #pragma unroll
    for (int n = 0; n < NBUF; n++) { T[n][0] = 0.0f; T[n][1] = 0.0f; }

    #pragma unroll
    for (int s = 0; s < NSLOT; s++) {
        float2 m = SM2(s);
        float tb0 = (m.x > 0.5f) ? 1.0f : 0.0f;
        float tb1 = (m.y > 0.5f) ? 1.0f : 0.0f;
        #pragma unroll
        for (int n = 0; n < NBUF; n++) {
            float aH = sAttnH[s][n];
            T[n][0] = fmaf(tb0, aH, T[n][0]);
            T[n][1] = fmaf(tb1, aH, T[n][1]);
        }
    }

    #pragma unroll
    for (int n = 0; n < NBUF; n++) {
        float2 p = SM2(7+n);
        const float An = sA[n];
        {
            float pc  = fminf(fmaxf(p.x, EPSF), OMEPSF);
            float lp  = __logf(pc);
            float l1m = __logf(1.0f - pc);     // == log1p(-p) in fp32 (Sterbenz)
            acc[0] = fmaf(-T[n][0], lp, acc[0]);
            acc[0] = fmaf(T[n][0] - An, l1m, acc[0]);
        }
        {
            float pc  = fminf(fmaxf(p.y, EPSF), OMEPSF);
            float lp  = __logf(pc);
            float l1m = __logf(1.0f - pc);
            acc[1] = fmaf(-T[n][1], lp, acc[1]);
            acc[1] = fmaf(T[n][1] - An, l1m, acc[1]);
        }
    }

    // ================= Phase B: V + tgt (needs group 1) =================
    asm volatile("cp.async.wait_group 1;\n" ::: "memory");
    __syncthreads();

    float V[NBUF][2];
    #pragma unroll
    for (int n = 0; n < NBUF; n++) { V[n][0] = 0.0f; V[n][1] = 0.0f; }

    #pragma unroll
    for (int s = 0; s < NSLOT; s++) {
        float2 v = SM2(12+s);
        float vb0 = (v.x > 0.5f) ? 1.0f : 0.0f;
        float vb1 = (v.y > 0.5f) ? 1.0f : 0.0f;
        #pragma unroll
        for (int n = 0; n < NBUF; n++) {
            float aK = sAttnK[s][n];
            V[n][0] = fmaf(vb0, aK, V[n][0]);
            V[n][1] = fmaf(vb1, aK, V[n][1]);
        }
    }

    float tg[CC][2];
    #pragma unroll
    for (int c = 0; c < CC; c++) {
        float2 t = SM2(19+c);
        tg[c][0] = t.x; tg[c][1] = t.y;
    }

    // ================= Phase C: MSE (needs group 2) =================
    asm volatile("cp.async.wait_group 0;\n" ::: "memory");
    __syncthreads();

    #pragma unroll
    for (int n = 0; n < NBUF; n++) {
        float d20 = 0.0f, d21 = 0.0f;
        #pragma unroll
        for (int c = 0; c < CC; c++) {
            float2 r = SM2(22 + n*CC + c);
            float dd0 = r.x - tg[c][0];
            float dd1 = r.y - tg[c][1];
            d20 = fmaf(dd0, dd0, d20);
            d21 = fmaf(dd1, dd1, d21);
        }
        acc[0] = fmaf(V[n][0], d20, acc[0]);
        acc[1] = fmaf(V[n][1], d21, acc[1]);
    }

    // ================= block reduction =================
    float tot = acc[0] + acc[1];
    #pragma unroll
    for (int o = 16; o > 0; o >>= 1)
        tot += __shfl_down_sync(0xffffffffu, tot, o);

    if ((tid & 31) == 0) wsum[tid >> 5] = tot;
    __syncthreads();

    if (tid == 0) {
        float s = 0.0f;
        #pragma unroll
        for (int i = 0; i < TPB / 32; i++) s += wsum[i];
        g_partials[blockIdx.x] = s;
        __threadfence();
        unsigned prev = atomicAdd(&g_ticket, 1u);
        isLast = (prev == GRID_MAIN - 1);
    }
    __syncthreads();

    // ================= last block: final deterministic reduction =================
    if (isLast) {
        float v0 = 0.0f, v1 = 0.0f, v2 = 0.0f;
        #pragma unroll 1
        for (int i = tid; i < GRID_MAIN; i += TPB * 3) {
            v0 += g_partials[i];
            v1 += g_partials[i + TPB];
            v2 += g_partials[i + 2*TPB];
        }
        float v = (v0 + v1) + v2;
        #pragma unroll
        for (int o = 16; o > 0; o >>= 1)
            v += __shfl_down_sync(0xffffffffu, v, o);
        if ((tid & 31) == 0) wsum[tid >> 5] = v;
        __syncthreads();
        if (tid == 0) {
            float s = 0.0f;
            #pragma unroll
            for (int i = 0; i < TPB / 32; i++) s += wsum[i];
            // total / (B*(F-1)*NB*NS) * LOSS_WEIGHT = total * 20/1400
            out[0] = s * (20.0f / 1400.0f);
            atomicExch(&g_ticket, 0u);          // reset for next graph replay
        }
    }
}

extern "C" void kernel_launch(void* const* d_in, const int* in_sizes, int n_in,
                              void* d_out, int out_size)
{
    const float* seg   = (const float*)d_in[0];  // segmentations   [B,F,NB,H,W]
    const float* masks = (const float*)d_in[1];  // masks           [B,F,NS,H,W]
    const float* rec   = (const float*)d_in[2];  // reconstructions [B,F,NB,C,H,W]
    const float* tgt   = (const float*)d_in[3];  // rec_tgt         [B,F,C,H,W]
    const float* vis   = (const float*)d_in[4];  // masks_vis       [B,F,NS,H,W]
    const float* attn  = (const float*)d_in[5];  // attn_index      [B,F,NS,NB]
    (void)in_sizes; (void)n_in; (void)out_size;

    em_main<<<GRID_MAIN, TPB>>>(seg, masks, rec, tgt, vis, attn, (float*)d_out);
}